// round 8
// baseline (speedup 1.0000x reference)
#include <cuda_runtime.h>
#include <cuda_bf16.h>
#include <cstdint>

// Problem constants
#define NN   4096
#define DD   128
#define HH   8
#define ALPHA 0.2f
#define LN_EPS 1e-5f
#define NJC  256           // 256 k-chunks of 16 j

typedef unsigned long long u64;

// ---------------- scratch (device globals; no allocation allowed) ----------------
// Wh^T in m16n8k16 B-fragment order, hi/lo interleaved per uint4:
// bf16 elem idx = ((((h*NJC + jc)*32 + lane)*16 + dt)*4 + comp)*2 + half
//   comp: 0=b0hi 1=b1hi 2=b0lo 3=b1lo ; b-reg = kk>>3 ; half = kk&1
//   lane = (d&7)*4 + ((kk&7)>>1) ; dt = d>>3 ; kk = j&15 ; jc = j>>4
// => per (h,jc): 32 lanes x 16 dt uint4  = 512 uint4
__device__ __nv_bfloat16 g_whB[(size_t)HH * NJC * 32 * 16 * 8];   // 16.8 MB
__device__ float4   g_fq [HH * NN];                 // (f1, e^f1, e^{a f1}, 0)
__device__ float4   g_fk [HH * NN];                 // (f2, e^f2, e^{a f2}, 0)
__device__ float    g_cat[(size_t)NN * (HH * DD)];  // [n][h*128+d], 16 MB
__device__ unsigned g_adjbits[NN * (NN / 32)];      // bit-packed adj, 2 MB

// ---------------- helpers ----------------
__device__ __forceinline__ u64 pack2(float x, float y) {
    u64 r; asm("mov.b64 %0, {%1, %2};" : "=l"(r) : "f"(x), "f"(y)); return r;
}
__device__ __forceinline__ float2 unpack2(u64 v) {
    float2 r; asm("mov.b64 {%0, %1}, %2;" : "=f"(r.x), "=f"(r.y) : "l"(v)); return r;
}
__device__ __forceinline__ u64 ffma2(u64 a, u64 b, u64 c) {
    u64 d; asm("fma.rn.f32x2 %0, %1, %2, %3;" : "=l"(d) : "l"(a), "l"(b), "l"(c)); return d;
}
__device__ __forceinline__ float elu1(float x) { return x > 0.f ? x : expm1f(x); }
__device__ __forceinline__ uint32_t bf2_bits(__nv_bfloat162 v) {
    return *reinterpret_cast<uint32_t*>(&v);
}

// m16n8k16 bf16 mma: D(f32) += A(bf16,row) * B(bf16,col)
__device__ __forceinline__ void mma_bf16(float c[4],
                                         uint32_t a0, uint32_t a1, uint32_t a2, uint32_t a3,
                                         uint32_t b0, uint32_t b1) {
    asm volatile(
        "mma.sync.aligned.m16n8k16.row.col.f32.bf16.bf16.f32 "
        "{%0,%1,%2,%3}, {%4,%5,%6,%7}, {%8,%9}, {%0,%1,%2,%3};"
        : "+f"(c[0]), "+f"(c[1]), "+f"(c[2]), "+f"(c[3])
        : "r"(a0), "r"(a1), "r"(a2), "r"(a3), "r"(b0), "r"(b1));
}

// =================================================================
// Kernel 0: bit-pack adjacency. One warp per 32 columns.
// =================================================================
__global__ void pack_kernel(const int* __restrict__ adj) {
    int w    = blockIdx.x * 8 + (threadIdx.x >> 5);
    int lane = threadIdx.x & 31;
    int av = adj[(size_t)w * 32 + lane];
    unsigned m = __ballot_sync(0xffffffffu, av > 0);
    if (lane == 0) g_adjbits[w] = m;
}

// =================================================================
// Kernel 1: Wh = nodes @ W[h]; writes
//   - g_whB : bf16 hi/lo B-fragments for the attention MMA
//   - g_fq/g_fk : f1/f2 + exp factors
// grid (64, 8), block 256. 64-node tile per CTA.
// =================================================================
__global__ void wh_kernel(const float* __restrict__ nodes, const float* __restrict__ W,
                          const float* __restrict__ a1, const float* __restrict__ a2) {
    __shared__ float ns[64][DD];
    const int h  = blockIdx.y;
    const int nb = blockIdx.x * 64;
    const int tid = threadIdx.x;

#pragma unroll
    for (int i = 0; i < 8; i++) {
        int f  = tid + 256 * i;
        int r  = f >> 5, c4 = f & 31;
        *(float4*)&ns[r][c4 * 4] = *(const float4*)&nodes[(size_t)(nb + r) * DD + c4 * 4];
    }
    __syncthreads();

    const int dg = tid & 31;   // lane: dims dg*4 .. dg*4+3
    const int ng = tid >> 5;   // warp: nodes ng*8 .. ng*8+7
    const float* Wb = W + (size_t)h * DD * DD;

    u64 acc[8][2];
#pragma unroll
    for (int n = 0; n < 8; n++) { acc[n][0] = 0ULL; acc[n][1] = 0ULL; }

#pragma unroll 4
    for (int k = 0; k < DD; k++) {
        float4 w4 = __ldg((const float4*)&Wb[k * DD + dg * 4]);
        u64 wxy = pack2(w4.x, w4.y);
        u64 wzw = pack2(w4.z, w4.w);
#pragma unroll
        for (int n = 0; n < 8; n++) {
            float s = ns[ng * 8 + n][k];
            u64 ss = pack2(s, s);
            acc[n][0] = ffma2(ss, wxy, acc[n][0]);
            acc[n][1] = ffma2(ss, wzw, acc[n][1]);
        }
    }

    float4 wh4[8];
#pragma unroll
    for (int n = 0; n < 8; n++) {
        float2 a = unpack2(acc[n][0]);
        float2 b = unpack2(acc[n][1]);
        wh4[n] = make_float4(a.x, a.y, b.x, b.y);
    }

    // ---- f1/f2 + exp factors ----
    float4 A1 = __ldg((const float4*)&a1[h * DD + dg * 4]);
    float4 A2 = __ldg((const float4*)&a2[h * DD + dg * 4]);
    float s1[8], s2[8];
#pragma unroll
    for (int n = 0; n < 8; n++) {
        s1[n] = wh4[n].x * A1.x + wh4[n].y * A1.y + wh4[n].z * A1.z + wh4[n].w * A1.w;
        s2[n] = wh4[n].x * A2.x + wh4[n].y * A2.y + wh4[n].z * A2.z + wh4[n].w * A2.w;
    }
#pragma unroll
    for (int o = 16; o > 0; o >>= 1) {
#pragma unroll
        for (int n = 0; n < 8; n++) {
            s1[n] += __shfl_xor_sync(0xffffffffu, s1[n], o);
            s2[n] += __shfl_xor_sync(0xffffffffu, s2[n], o);
        }
    }
    if (dg < 8) {
        float v1 = s1[0], v2 = s2[0];
#pragma unroll
        for (int n = 1; n < 8; n++)
            if (dg == n) { v1 = s1[n]; v2 = s2[n]; }
        int node = nb + ng * 8 + dg;
        g_fq[h * NN + node] = make_float4(v1, expf(v1), expf(ALPHA * v1), 0.f);
        g_fk[h * NN + node] = make_float4(v2, expf(v2), expf(ALPHA * v2), 0.f);
    }

    // ---- bf16 hi/lo B-fragment write ----
#pragma unroll
    for (int n = 0; n < 8; n++) {
        int j  = nb + ng * 8 + n;
        int jc = j >> 4, kk = j & 15;
        int comp = kk >> 3;          // which b-reg (hi slot; +2 for lo)
        int half = kk & 1;
        int lk   = (kk & 7) >> 1;
        size_t cb = ((size_t)(h * NJC + jc)) * 32;
        float vals[4] = {wh4[n].x, wh4[n].y, wh4[n].z, wh4[n].w};
#pragma unroll
        for (int q = 0; q < 4; q++) {
            int d = dg * 4 + q;
            int dt = d >> 3;
            int lane2 = (d & 7) * 4 + lk;
            size_t ei = (((cb + lane2) * 16 + dt) * 4 + comp) * 2 + half;
            float v = vals[q];
            __nv_bfloat16 hv = __float2bfloat16(v);
            g_whB[ei]     = hv;                                        // hi (comp)
            g_whB[ei + 4] = __float2bfloat16(v - __bfloat162float(hv)); // lo (comp+2)
        }
    }
}

// =================================================================
// Kernel 2: attention, operand-flipped (P = A operand), barrier-free.
// grid (32, 8): 128-query tile per CTA for head h. block 256.
// Warp wid owns q in [qbase + wid*16, +16); all 128 d via 16 n8 tiles.
// Lane (r4, c4): q = {r4, r4+8}, j = {2c4, 2c4+1, 2c4+8, 2c4+9} per k16.
// =================================================================
__global__ void __launch_bounds__(256, 2) attn_kernel() {
    const int h     = blockIdx.y;
    const int qbase = blockIdx.x * 128;
    const int tid   = threadIdx.x;
    const int wid   = tid >> 5;
    const int lane  = tid & 31;
    const int r4 = lane >> 2;
    const int c4 = lane & 3;

    const int q_lo = qbase + wid * 16 + r4;
    const int q_hi = q_lo + 8;

    const float4 fqlo = __ldg(&g_fq[h * NN + q_lo]);
    const float4 fqhi = __ldg(&g_fq[h * NN + q_hi]);

    float acc[16][4];
#pragma unroll
    for (int dt = 0; dt < 16; dt++)
#pragma unroll
        for (int i = 0; i < 4; i++) acc[dt][i] = 0.f;
    float llo = 0.f, lhi = 0.f;

    const float4*   fkb = g_fk + h * NN;
    const unsigned* abl = g_adjbits + (size_t)q_lo * (NN / 32);
    const unsigned* abh = g_adjbits + (size_t)q_hi * (NN / 32);
    // FIX: per-(h,jc) block = 512 uint4 (32 lanes x 16 dt); lane stride = 16 uint4
    const uint4*    Bb  = (const uint4*)g_whB + (size_t)h * NJC * 512 + lane * 16;

    unsigned wlo = 0, whi = 0;

#define PVAL(FQ, KV, BIT, W) \
    ({ float _t = (FQ).x + (KV).x; \
       float _p = (_t >= 0.f) ? (FQ).y * (KV).y : (FQ).z * (KV).z; \
       (((W) >> (BIT)) & 1u) ? _p : 0.f; })

    for (int jc = 0; jc < NJC; jc++) {
        if ((jc & 1) == 0) {
            wlo = __ldg(&abl[jc >> 1]);
            whi = __ldg(&abh[jc >> 1]);
        }
        const int j0 = jc * 16 + 2 * c4;
        const int sh = ((jc & 1) << 4) + 2 * c4;

        float4 k0 = __ldg(&fkb[j0]);
        float4 k1 = __ldg(&fkb[j0 + 1]);
        float4 k2 = __ldg(&fkb[j0 + 8]);
        float4 k3 = __ldg(&fkb[j0 + 9]);

        // 8 score values in exact A-fragment positions
        float pl0 = PVAL(fqlo, k0, sh,     wlo);
        float pl1 = PVAL(fqlo, k1, sh + 1, wlo);
        float pl2 = PVAL(fqlo, k2, sh + 8, wlo);
        float pl3 = PVAL(fqlo, k3, sh + 9, wlo);
        float ph0 = PVAL(fqhi, k0, sh,     whi);
        float ph1 = PVAL(fqhi, k1, sh + 1, whi);
        float ph2 = PVAL(fqhi, k2, sh + 8, whi);
        float ph3 = PVAL(fqhi, k3, sh + 9, whi);

        llo += (pl0 + pl1) + (pl2 + pl3);
        lhi += (ph0 + ph1) + (ph2 + ph3);

        // hi/lo bf16 split, packed into A-frag regs
        __nv_bfloat162 hA0 = __floats2bfloat162_rn(pl0, pl1);
        __nv_bfloat162 hA1 = __floats2bfloat162_rn(ph0, ph1);
        __nv_bfloat162 hA2 = __floats2bfloat162_rn(pl2, pl3);
        __nv_bfloat162 hA3 = __floats2bfloat162_rn(ph2, ph3);
        __nv_bfloat162 lA0 = __floats2bfloat162_rn(pl0 - __low2float(hA0), pl1 - __high2float(hA0));
        __nv_bfloat162 lA1 = __floats2bfloat162_rn(ph0 - __low2float(hA1), ph1 - __high2float(hA1));
        __nv_bfloat162 lA2 = __floats2bfloat162_rn(pl2 - __low2float(hA2), pl3 - __high2float(hA2));
        __nv_bfloat162 lA3 = __floats2bfloat162_rn(ph2 - __low2float(hA3), ph3 - __high2float(hA3));
        uint32_t ah0 = bf2_bits(hA0), ah1 = bf2_bits(hA1), ah2 = bf2_bits(hA2), ah3 = bf2_bits(hA3);
        uint32_t al0 = bf2_bits(lA0), al1 = bf2_bits(lA1), al2 = bf2_bits(lA2), al3 = bf2_bits(lA3);

        const uint4* Bp = Bb + (size_t)jc * 512;
#pragma unroll
        for (int dt = 0; dt < 16; dt++) {
            uint4 b = __ldg(&Bp[dt]);
            mma_bf16(acc[dt], ah0, ah1, ah2, ah3, b.x, b.y);   // Phi * Whhi
            mma_bf16(acc[dt], al0, al1, al2, al3, b.x, b.y);   // Plo * Whhi
            mma_bf16(acc[dt], ah0, ah1, ah2, ah3, b.z, b.w);   // Phi * Whlo
        }
    }
#undef PVAL

    // softmax denominators: lanes sharing r4 (c4=0..3) cover all j
    llo += __shfl_xor_sync(0xffffffffu, llo, 1);
    llo += __shfl_xor_sync(0xffffffffu, llo, 2);
    lhi += __shfl_xor_sync(0xffffffffu, lhi, 1);
    lhi += __shfl_xor_sync(0xffffffffu, lhi, 2);
    const float inv_lo = 1.f / llo;
    const float inv_hi = 1.f / lhi;

    // normalize + ELU + write concat layout [q][h*128+d]
    float* rowl = g_cat + (size_t)q_lo * (HH * DD) + h * DD;
    float* rowh = g_cat + (size_t)q_hi * (HH * DD) + h * DD;
#pragma unroll
    for (int dt = 0; dt < 16; dt++) {
        int d0 = dt * 8 + 2 * c4;
        *(float2*)&rowl[d0] = make_float2(elu1(acc[dt][0] * inv_lo), elu1(acc[dt][1] * inv_lo));
        *(float2*)&rowh[d0] = make_float2(elu1(acc[dt][2] * inv_hi), elu1(acc[dt][3] * inv_hi));
    }
}

// =================================================================
// Kernel 3: x = elu(cat @ W1 + b1); out = LN(nodes + x)
// grid 512 (8 nodes/CTA), block 256 (split-k halves)
// =================================================================
__global__ void out_kernel(const float* __restrict__ nodes,
                           const float* __restrict__ W1,
                           const float* __restrict__ b1,
                           const float* __restrict__ gamma,
                           const float* __restrict__ beta,
                           float* __restrict__ out) {
    __shared__ float cs[8][1024];    // 32 KB
    __shared__ float part[8][DD];    //  4 KB
    __shared__ float rbuf[8][DD];    //  4 KB

    const int nb  = blockIdx.x * 8;
    const int tid = threadIdx.x;
    const int kh  = tid >> 7;        // which k-half
    const int col = tid & 127;

#pragma unroll
    for (int i = 0; i < 8; i++) {
        int f = tid + 256 * i;
        int r = f >> 8, c4 = f & 255;
        *(float4*)&cs[r][c4 * 4] = *(const float4*)&g_cat[(size_t)(nb + r) * 1024 + c4 * 4];
    }
    __syncthreads();

    u64 acc2[8];
#pragma unroll
    for (int n = 0; n < 8; n++) acc2[n] = 0ULL;

    const int kbeg = kh * 512;
    for (int k = kbeg; k < kbeg + 512; k += 4) {
        float w0  = __ldg(&W1[(size_t)(k + 0) * DD + col]);
        float w1v = __ldg(&W1[(size_t)(k + 1) * DD + col]);
        float w2  = __ldg(&W1[(size_t)(k + 2) * DD + col]);
        float w3  = __ldg(&W1[(size_t)(k + 3) * DD + col]);
        u64 ww01 = pack2(w0, w1v);
        u64 ww23 = pack2(w2, w3);
#pragma unroll
        for (int n = 0; n < 8; n++) {
            float4 c = *(float4*)&cs[n][k];
            acc2[n] = ffma2(pack2(c.x, c.y), ww01, acc2[n]);
            acc2[n] = ffma2(pack2(c.z, c.w), ww23, acc2[n]);
        }
    }

    float acc[8];
#pragma unroll
    for (int n = 0; n < 8; n++) {
        float2 t = unpack2(acc2[n]);
        acc[n] = t.x + t.y;
    }

    if (kh == 1) {
#pragma unroll
        for (int n = 0; n < 8; n++) part[n][col] = acc[n];
    }
    __syncthreads();
    if (kh == 0) {
        float bb = __ldg(&b1[col]);
#pragma unroll
        for (int n = 0; n < 8; n++) {
            float x = elu1(acc[n] + part[n][col] + bb);
            rbuf[n][col] = nodes[(size_t)(nb + n) * DD + col] + x;
        }
    }
    __syncthreads();

    const int w    = tid >> 5;
    const int lane = tid & 31;
    float4 G = __ldg((const float4*)&gamma[lane * 4]);
    float4 B = __ldg((const float4*)&beta[lane * 4]);
    {
        float4 r = *(float4*)&rbuf[w][lane * 4];
        float s  = r.x + r.y + r.z + r.w;
        float ss = r.x * r.x + r.y * r.y + r.z * r.z + r.w * r.w;
#pragma unroll
        for (int o = 16; o > 0; o >>= 1) {
            s  += __shfl_xor_sync(0xffffffffu, s, o);
            ss += __shfl_xor_sync(0xffffffffu, ss, o);
        }
        float mu   = s * (1.f / DD);
        float var  = ss * (1.f / DD) - mu * mu;
        float rstd = rsqrtf(var + LN_EPS);
        float4 o4;
        o4.x = (r.x - mu) * rstd * G.x + B.x;
        o4.y = (r.y - mu) * rstd * G.y + B.y;
        o4.z = (r.z - mu) * rstd * G.z + B.z;
        o4.w = (r.w - mu) * rstd * G.w + B.w;
        *(float4*)&out[(size_t)(nb + w) * DD + lane * 4] = o4;
    }
}

// =================================================================
extern "C" void kernel_launch(void* const* d_in, const int* in_sizes, int n_in,
                              void* d_out, int out_size) {
    const float* nodes = (const float*)d_in[0];
    const int*   adj   = (const int*)  d_in[1];
    const float* W     = (const float*)d_in[2];
    const float* a1    = (const float*)d_in[3];
    const float* a2    = (const float*)d_in[4];
    const float* W1    = (const float*)d_in[5];
    const float* b1    = (const float*)d_in[6];
    const float* gamma = (const float*)d_in[7];
    const float* beta  = (const float*)d_in[8];
    float* out = (float*)d_out;

    pack_kernel<<<NN * (NN / 32) / 8, 256>>>(adj);
    wh_kernel  <<<dim3(NN / 64, HH), 256>>>(nodes, W, a1, a2);
    attn_kernel<<<dim3(NN / 128, HH), 256>>>();
    out_kernel <<<NN / 8, 256>>>(nodes, W1, b1, gamma, beta, out);
}

// round 9
// speedup vs baseline: 2.0029x; 2.0029x over previous
#include <cuda_runtime.h>
#include <cuda_bf16.h>
#include <cstdint>

// Problem constants
#define NN   4096
#define DD   128
#define HH   8
#define ALPHA 0.2f
#define LN_EPS 1e-5f
#define NJC  256           // 256 k-chunks of 16 j

typedef unsigned long long u64;

// ---------------- scratch (device globals; no allocation allowed) ----------------
// Wh^T in m16n8k16 B-fragment order, hi/lo interleaved per uint4, COALESCED:
// bf16 elem idx = ((((h*NJC + jc)*16 + dt)*32 + lane)*4 + comp)*2 + half
//   comp: 0=b0hi 1=b1hi 2=b0lo 3=b1lo ; b-reg = kk>>3 ; half = kk&1
//   lane = (d&7)*4 + ((kk&7)>>1) ; dt = d>>3 ; kk = j&15 ; jc = j>>4
// A warp-wide uint4 load of one dt is lane-contiguous: 512 B = 4 lines.
__device__ __nv_bfloat16 g_whB[(size_t)HH * NJC * 16 * 32 * 8];   // 16.8 MB
__device__ float4   g_fq [HH * NN];                 // (f1, e^f1, e^{a f1}, 0)
__device__ float4   g_fk [HH * NN];                 // (f2, e^f2, e^{a f2}, 0)
__device__ float    g_cat[(size_t)NN * (HH * DD)];  // [n][h*128+d], 16 MB
__device__ unsigned g_adjbits[NN * (NN / 32)];      // bit-packed adj, 2 MB

// ---------------- helpers ----------------
__device__ __forceinline__ u64 pack2(float x, float y) {
    u64 r; asm("mov.b64 %0, {%1, %2};" : "=l"(r) : "f"(x), "f"(y)); return r;
}
__device__ __forceinline__ float2 unpack2(u64 v) {
    float2 r; asm("mov.b64 {%0, %1}, %2;" : "=f"(r.x), "=f"(r.y) : "l"(v)); return r;
}
__device__ __forceinline__ u64 ffma2(u64 a, u64 b, u64 c) {
    u64 d; asm("fma.rn.f32x2 %0, %1, %2, %3;" : "=l"(d) : "l"(a), "l"(b), "l"(c)); return d;
}
__device__ __forceinline__ float elu1(float x) { return x > 0.f ? x : expm1f(x); }
__device__ __forceinline__ uint32_t bf2_bits(__nv_bfloat162 v) {
    return *reinterpret_cast<uint32_t*>(&v);
}

// m16n8k16 bf16 mma: D(f32) += A(bf16,row) * B(bf16,col)
__device__ __forceinline__ void mma_bf16(float c[4],
                                         uint32_t a0, uint32_t a1, uint32_t a2, uint32_t a3,
                                         uint32_t b0, uint32_t b1) {
    asm volatile(
        "mma.sync.aligned.m16n8k16.row.col.f32.bf16.bf16.f32 "
        "{%0,%1,%2,%3}, {%4,%5,%6,%7}, {%8,%9}, {%0,%1,%2,%3};"
        : "+f"(c[0]), "+f"(c[1]), "+f"(c[2]), "+f"(c[3])
        : "r"(a0), "r"(a1), "r"(a2), "r"(a3), "r"(b0), "r"(b1));
}

// =================================================================
// Kernel 0: bit-pack adjacency. One warp per 32 columns.
// =================================================================
__global__ void pack_kernel(const int* __restrict__ adj) {
    int w    = blockIdx.x * 8 + (threadIdx.x >> 5);
    int lane = threadIdx.x & 31;
    int av = adj[(size_t)w * 32 + lane];
    unsigned m = __ballot_sync(0xffffffffu, av > 0);
    if (lane == 0) g_adjbits[w] = m;
}

// =================================================================
// Kernel 1: Wh = nodes @ W[h]; writes
//   - g_whB : bf16 hi/lo B-fragments (coalesced layout)
//   - g_fq/g_fk : f1/f2 + exp factors
// grid (64, 8), block 256. 64-node tile per CTA.
// =================================================================
__global__ void wh_kernel(const float* __restrict__ nodes, const float* __restrict__ W,
                          const float* __restrict__ a1, const float* __restrict__ a2) {
    __shared__ float ns[64][DD];
    const int h  = blockIdx.y;
    const int nb = blockIdx.x * 64;
    const int tid = threadIdx.x;

#pragma unroll
    for (int i = 0; i < 8; i++) {
        int f  = tid + 256 * i;
        int r  = f >> 5, c4 = f & 31;
        *(float4*)&ns[r][c4 * 4] = *(const float4*)&nodes[(size_t)(nb + r) * DD + c4 * 4];
    }
    __syncthreads();

    const int dg = tid & 31;   // lane: dims dg*4 .. dg*4+3
    const int ng = tid >> 5;   // warp: nodes ng*8 .. ng*8+7
    const float* Wb = W + (size_t)h * DD * DD;

    u64 acc[8][2];
#pragma unroll
    for (int n = 0; n < 8; n++) { acc[n][0] = 0ULL; acc[n][1] = 0ULL; }

#pragma unroll 4
    for (int k = 0; k < DD; k++) {
        float4 w4 = __ldg((const float4*)&Wb[k * DD + dg * 4]);
        u64 wxy = pack2(w4.x, w4.y);
        u64 wzw = pack2(w4.z, w4.w);
#pragma unroll
        for (int n = 0; n < 8; n++) {
            float s = ns[ng * 8 + n][k];
            u64 ss = pack2(s, s);
            acc[n][0] = ffma2(ss, wxy, acc[n][0]);
            acc[n][1] = ffma2(ss, wzw, acc[n][1]);
        }
    }

    float4 wh4[8];
#pragma unroll
    for (int n = 0; n < 8; n++) {
        float2 a = unpack2(acc[n][0]);
        float2 b = unpack2(acc[n][1]);
        wh4[n] = make_float4(a.x, a.y, b.x, b.y);
    }

    // ---- f1/f2 + exp factors ----
    float4 A1 = __ldg((const float4*)&a1[h * DD + dg * 4]);
    float4 A2 = __ldg((const float4*)&a2[h * DD + dg * 4]);
    float s1[8], s2[8];
#pragma unroll
    for (int n = 0; n < 8; n++) {
        s1[n] = wh4[n].x * A1.x + wh4[n].y * A1.y + wh4[n].z * A1.z + wh4[n].w * A1.w;
        s2[n] = wh4[n].x * A2.x + wh4[n].y * A2.y + wh4[n].z * A2.z + wh4[n].w * A2.w;
    }
#pragma unroll
    for (int o = 16; o > 0; o >>= 1) {
#pragma unroll
        for (int n = 0; n < 8; n++) {
            s1[n] += __shfl_xor_sync(0xffffffffu, s1[n], o);
            s2[n] += __shfl_xor_sync(0xffffffffu, s2[n], o);
        }
    }
    if (dg < 8) {
        float v1 = s1[0], v2 = s2[0];
#pragma unroll
        for (int n = 1; n < 8; n++)
            if (dg == n) { v1 = s1[n]; v2 = s2[n]; }
        int node = nb + ng * 8 + dg;
        g_fq[h * NN + node] = make_float4(v1, expf(v1), expf(ALPHA * v1), 0.f);
        g_fk[h * NN + node] = make_float4(v2, expf(v2), expf(ALPHA * v2), 0.f);
    }

    // ---- bf16 hi/lo B-fragment write (coalesced [jc][dt][lane] layout) ----
#pragma unroll
    for (int n = 0; n < 8; n++) {
        int j  = nb + ng * 8 + n;
        int jc = j >> 4, kk = j & 15;
        int comp = kk >> 3;          // which b-reg (hi slot; +2 for lo)
        int half = kk & 1;
        int lk   = (kk & 7) >> 1;
        size_t cb = ((size_t)(h * NJC + jc)) * 16;
        float vals[4] = {wh4[n].x, wh4[n].y, wh4[n].z, wh4[n].w};
#pragma unroll
        for (int q = 0; q < 4; q++) {
            int d = dg * 4 + q;
            int dt = d >> 3;
            int lane2 = (d & 7) * 4 + lk;
            size_t ei = (((cb + dt) * 32 + lane2) * 4 + comp) * 2 + half;
            float v = vals[q];
            __nv_bfloat16 hv = __float2bfloat16(v);
            g_whB[ei]     = hv;                                        // hi (comp)
            g_whB[ei + 4] = __float2bfloat16(v - __bfloat162float(hv)); // lo (comp+2)
        }
    }
}

// =================================================================
// Kernel 2: attention, operand-flipped (P = A operand), barrier-free.
// grid (32, 8): 128-query tile per CTA for head h. block 256.
// Warp wid owns q in [qbase + wid*16, +16); all 128 d via 16 n8 tiles.
// Lane (r4, c4): q = {r4, r4+8}, j = {2c4, 2c4+1, 2c4+8, 2c4+9} per k16.
// B loads are warp-coalesced (4 lines per LDG.128) and batched 8-deep.
// =================================================================
__global__ void __launch_bounds__(256, 2) attn_kernel() {
    const int h     = blockIdx.y;
    const int qbase = blockIdx.x * 128;
    const int tid   = threadIdx.x;
    const int wid   = tid >> 5;
    const int lane  = tid & 31;
    const int r4 = lane >> 2;
    const int c4 = lane & 3;

    const int q_lo = qbase + wid * 16 + r4;
    const int q_hi = q_lo + 8;

    const float4 fqlo = __ldg(&g_fq[h * NN + q_lo]);
    const float4 fqhi = __ldg(&g_fq[h * NN + q_hi]);

    float acc[16][4];
#pragma unroll
    for (int dt = 0; dt < 16; dt++)
#pragma unroll
        for (int i = 0; i < 4; i++) acc[dt][i] = 0.f;
    float llo = 0.f, lhi = 0.f;

    const float4*   fkb = g_fk + h * NN;
    const unsigned* abl = g_adjbits + (size_t)q_lo * (NN / 32);
    const unsigned* abh = g_adjbits + (size_t)q_hi * (NN / 32);
    // per-(h,jc): 16 dt x 32 lanes uint4; lane offset once
    const uint4*    Bb  = (const uint4*)g_whB + (size_t)h * NJC * 512 + lane;

    unsigned wlo = 0, whi = 0;

#define PVAL(FQ, KV, BIT, W) \
    ({ float _t = (FQ).x + (KV).x; \
       float _p = (_t >= 0.f) ? (FQ).y * (KV).y : (FQ).z * (KV).z; \
       (((W) >> (BIT)) & 1u) ? _p : 0.f; })

    for (int jc = 0; jc < NJC; jc++) {
        if ((jc & 1) == 0) {
            wlo = __ldg(&abl[jc >> 1]);
            whi = __ldg(&abh[jc >> 1]);
        }
        const int j0 = jc * 16 + 2 * c4;
        const int sh = ((jc & 1) << 4) + 2 * c4;

        float4 k0 = __ldg(&fkb[j0]);
        float4 k1 = __ldg(&fkb[j0 + 1]);
        float4 k2 = __ldg(&fkb[j0 + 8]);
        float4 k3 = __ldg(&fkb[j0 + 9]);

        // 8 score values in exact A-fragment positions
        float pl0 = PVAL(fqlo, k0, sh,     wlo);
        float pl1 = PVAL(fqlo, k1, sh + 1, wlo);
        float pl2 = PVAL(fqlo, k2, sh + 8, wlo);
        float pl3 = PVAL(fqlo, k3, sh + 9, wlo);
        float ph0 = PVAL(fqhi, k0, sh,     whi);
        float ph1 = PVAL(fqhi, k1, sh + 1, whi);
        float ph2 = PVAL(fqhi, k2, sh + 8, whi);
        float ph3 = PVAL(fqhi, k3, sh + 9, whi);

        llo += (pl0 + pl1) + (pl2 + pl3);
        lhi += (ph0 + ph1) + (ph2 + ph3);

        // hi/lo bf16 split, packed into A-frag regs
        __nv_bfloat162 hA0 = __floats2bfloat162_rn(pl0, pl1);
        __nv_bfloat162 hA1 = __floats2bfloat162_rn(ph0, ph1);
        __nv_bfloat162 hA2 = __floats2bfloat162_rn(pl2, pl3);
        __nv_bfloat162 hA3 = __floats2bfloat162_rn(ph2, ph3);
        __nv_bfloat162 lA0 = __floats2bfloat162_rn(pl0 - __low2float(hA0), pl1 - __high2float(hA0));
        __nv_bfloat162 lA1 = __floats2bfloat162_rn(ph0 - __low2float(hA1), ph1 - __high2float(hA1));
        __nv_bfloat162 lA2 = __floats2bfloat162_rn(pl2 - __low2float(hA2), pl3 - __high2float(hA2));
        __nv_bfloat162 lA3 = __floats2bfloat162_rn(ph2 - __low2float(hA3), ph3 - __high2float(hA3));
        uint32_t ah0 = bf2_bits(hA0), ah1 = bf2_bits(hA1), ah2 = bf2_bits(hA2), ah3 = bf2_bits(hA3);
        uint32_t al0 = bf2_bits(lA0), al1 = bf2_bits(lA1), al2 = bf2_bits(lA2), al3 = bf2_bits(lA3);

        const uint4* Bp = Bb + (size_t)jc * 512;

        // batch 1: dt 0..7 (8 coalesced loads, then 24 MMAs)
        uint4 b[8];
#pragma unroll
        for (int dt = 0; dt < 8; dt++) b[dt] = __ldg(&Bp[dt * 32]);
#pragma unroll
        for (int dt = 0; dt < 8; dt++) {
            mma_bf16(acc[dt], ah0, ah1, ah2, ah3, b[dt].x, b[dt].y);
            mma_bf16(acc[dt], al0, al1, al2, al3, b[dt].x, b[dt].y);
            mma_bf16(acc[dt], ah0, ah1, ah2, ah3, b[dt].z, b[dt].w);
        }
        // batch 2: dt 8..15
#pragma unroll
        for (int dt = 0; dt < 8; dt++) b[dt] = __ldg(&Bp[(dt + 8) * 32]);
#pragma unroll
        for (int dt = 0; dt < 8; dt++) {
            mma_bf16(acc[dt + 8], ah0, ah1, ah2, ah3, b[dt].x, b[dt].y);
            mma_bf16(acc[dt + 8], al0, al1, al2, al3, b[dt].x, b[dt].y);
            mma_bf16(acc[dt + 8], ah0, ah1, ah2, ah3, b[dt].z, b[dt].w);
        }
    }
#undef PVAL

    // softmax denominators: lanes sharing r4 (c4=0..3) cover all j
    llo += __shfl_xor_sync(0xffffffffu, llo, 1);
    llo += __shfl_xor_sync(0xffffffffu, llo, 2);
    lhi += __shfl_xor_sync(0xffffffffu, lhi, 1);
    lhi += __shfl_xor_sync(0xffffffffu, lhi, 2);
    const float inv_lo = 1.f / llo;
    const float inv_hi = 1.f / lhi;

    // normalize + ELU + write concat layout [q][h*128+d]
    float* rowl = g_cat + (size_t)q_lo * (HH * DD) + h * DD;
    float* rowh = g_cat + (size_t)q_hi * (HH * DD) + h * DD;
#pragma unroll
    for (int dt = 0; dt < 16; dt++) {
        int d0 = dt * 8 + 2 * c4;
        *(float2*)&rowl[d0] = make_float2(elu1(acc[dt][0] * inv_lo), elu1(acc[dt][1] * inv_lo));
        *(float2*)&rowh[d0] = make_float2(elu1(acc[dt][2] * inv_hi), elu1(acc[dt][3] * inv_hi));
    }
}

// =================================================================
// Kernel 3: x = elu(cat @ W1 + b1); out = LN(nodes + x)
// grid 512 (8 nodes/CTA), block 256 (split-k halves)
// =================================================================
__global__ void out_kernel(const float* __restrict__ nodes,
                           const float* __restrict__ W1,
                           const float* __restrict__ b1,
                           const float* __restrict__ gamma,
                           const float* __restrict__ beta,
                           float* __restrict__ out) {
    __shared__ float cs[8][1024];    // 32 KB
    __shared__ float part[8][DD];    //  4 KB
    __shared__ float rbuf[8][DD];    //  4 KB

    const int nb  = blockIdx.x * 8;
    const int tid = threadIdx.x;
    const int kh  = tid >> 7;        // which k-half
    const int col = tid & 127;

#pragma unroll
    for (int i = 0; i < 8; i++) {
        int f = tid + 256 * i;
        int r = f >> 8, c4 = f & 255;
        *(float4*)&cs[r][c4 * 4] = *(const float4*)&g_cat[(size_t)(nb + r) * 1024 + c4 * 4];
    }
    __syncthreads();

    u64 acc2[8];
#pragma unroll
    for (int n = 0; n < 8; n++) acc2[n] = 0ULL;

    const int kbeg = kh * 512;
    for (int k = kbeg; k < kbeg + 512; k += 4) {
        float w0  = __ldg(&W1[(size_t)(k + 0) * DD + col]);
        float w1v = __ldg(&W1[(size_t)(k + 1) * DD + col]);
        float w2  = __ldg(&W1[(size_t)(k + 2) * DD + col]);
        float w3  = __ldg(&W1[(size_t)(k + 3) * DD + col]);
        u64 ww01 = pack2(w0, w1v);
        u64 ww23 = pack2(w2, w3);
#pragma unroll
        for (int n = 0; n < 8; n++) {
            float4 c = *(float4*)&cs[n][k];
            acc2[n] = ffma2(pack2(c.x, c.y), ww01, acc2[n]);
            acc2[n] = ffma2(pack2(c.z, c.w), ww23, acc2[n]);
        }
    }

    float acc[8];
#pragma unroll
    for (int n = 0; n < 8; n++) {
        float2 t = unpack2(acc2[n]);
        acc[n] = t.x + t.y;
    }

    if (kh == 1) {
#pragma unroll
        for (int n = 0; n < 8; n++) part[n][col] = acc[n];
    }
    __syncthreads();
    if (kh == 0) {
        float bb = __ldg(&b1[col]);
#pragma unroll
        for (int n = 0; n < 8; n++) {
            float x = elu1(acc[n] + part[n][col] + bb);
            rbuf[n][col] = nodes[(size_t)(nb + n) * DD + col] + x;
        }
    }
    __syncthreads();

    const int w    = tid >> 5;
    const int lane = tid & 31;
    float4 G = __ldg((const float4*)&gamma[lane * 4]);
    float4 B = __ldg((const float4*)&beta[lane * 4]);
    {
        float4 r = *(float4*)&rbuf[w][lane * 4];
        float s  = r.x + r.y + r.z + r.w;
        float ss = r.x * r.x + r.y * r.y + r.z * r.z + r.w * r.w;
#pragma unroll
        for (int o = 16; o > 0; o >>= 1) {
            s  += __shfl_xor_sync(0xffffffffu, s, o);
            ss += __shfl_xor_sync(0xffffffffu, ss, o);
        }
        float mu   = s * (1.f / DD);
        float var  = ss * (1.f / DD) - mu * mu;
        float rstd = rsqrtf(var + LN_EPS);
        float4 o4;
        o4.x = (r.x - mu) * rstd * G.x + B.x;
        o4.y = (r.y - mu) * rstd * G.y + B.y;
        o4.z = (r.z - mu) * rstd * G.z + B.z;
        o4.w = (r.w - mu) * rstd * G.w + B.w;
        *(float4*)&out[(size_t)(nb + w) * DD + lane * 4] = o4;
    }
}

// =================================================================
extern "C" void kernel_launch(void* const* d_in, const int* in_sizes, int n_in,
                              void* d_out, int out_size) {
    const float* nodes = (const float*)d_in[0];
    const int*   adj   = (const int*)  d_in[1];
    const float* W     = (const float*)d_in[2];
    const float* a1    = (const float*)d_in[3];
    const float* a2    = (const float*)d_in[4];
    const float* W1    = (const float*)d_in[5];
    const float* b1    = (const float*)d_in[6];
    const float* gamma = (const float*)d_in[7];
    const float* beta  = (const float*)d_in[8];
    float* out = (float*)d_out;

    pack_kernel<<<NN * (NN / 32) / 8, 256>>>(adj);
    wh_kernel  <<<dim3(NN / 64, HH), 256>>>(nodes, W, a1, a2);
    attn_kernel<<<dim3(NN / 128, HH), 256>>>();
    out_kernel <<<NN / 8, 256>>>(nodes, W1, b1, gamma, beta, out);
}